// round 8
// baseline (speedup 1.0000x reference)
#include <cuda_runtime.h>
#include <math.h>
#include <stdint.h>

// Problem constants
#define BB 4
#define HH 16
#define LL 2048
#define DD 1024
#define ROWS_PER_B (HH * LL)          // 32768 rows of length LL per batch
#define CHUNKS 128
#define ROWS_PER_CHUNK (ROWS_PER_B / CHUNKS)  // 256
#define M_TOTAL (BB * LL)             // 8192

// Output packing (flattened tuple):
//   [0, 8388608)          hidden_states
//   [8388608, 8396800)    attention_mask
//   [8396800, 8404992)    tome_out (ones)
//   [8404992, 8413184)    learnable_01mask
#define OUT_HID   0
#define OUT_ATTN  (M_TOTAL * DD)            // 8388608
#define OUT_TOME  (OUT_ATTN + M_TOTAL)      // 8396800
#define OUT_MASK  (OUT_TOME + M_TOTAL)      // 8404992

// Device scratch (static globals — no allocation allowed)
__device__ float g_partial[BB * CHUNKS * LL];   // 4 MB   score partial sums
__device__ float g_imp[BB * LL];                // 32 KB  normalized importance
__device__ float g_mean[M_TOTAL];               // LN1 row mean
__device__ float g_rstd[M_TOTAL];               // LN1 row rstd
__device__ float g_h1[(size_t)M_TOTAL * DD];    // 33.5 MB  GEMM output

// ---------------------------------------------------------------------------
// K1: copy hidden_states -> out[0..]
// ---------------------------------------------------------------------------
__global__ void copy_hidden_kernel(const float4* __restrict__ src,
                                   float4* __restrict__ dst, int n4) {
    int i = blockIdx.x * blockDim.x + threadIdx.x;
    if (i < n4) dst[i] = src[i];
}

// ---------------------------------------------------------------------------
// K2: partial reduction of self_attention_scores over (H, Lq)
// grid (x = k-tile of 1024, y = row chunk, z = batch); 256 threads, float4/thr
// ---------------------------------------------------------------------------
__global__ void reduce_scores_kernel(const float* __restrict__ scores) {
    int b = blockIdx.z;
    int chunk = blockIdx.y;
    int k = blockIdx.x * 1024 + threadIdx.x * 4;

    const float* base = scores +
        ((size_t)(b * ROWS_PER_B + chunk * ROWS_PER_CHUNK)) * LL + k;

    float ax = 0.f, ay = 0.f, az = 0.f, aw = 0.f;
#pragma unroll 8
    for (int r = 0; r < ROWS_PER_CHUNK; r++) {
        float4 v = *(const float4*)(base + (size_t)r * LL);
        ax += v.x; ay += v.y; az += v.z; aw += v.w;
    }
    float4 o; o.x = ax; o.y = ay; o.z = az; o.w = aw;
    *(float4*)&g_partial[(size_t)(b * CHUNKS + chunk) * LL + k] = o;
}

// ---------------------------------------------------------------------------
// K3: finalize importance: combine partials, zero col0, min/max over cols 1:,
//     imp = (imp - min)/max, set col0 = 1.  One block (1024 thr) per batch.
// ---------------------------------------------------------------------------
__global__ void finalize_imp_kernel() {
    int b = blockIdx.x;
    int tid = threadIdx.x;   // 1024 threads; each handles k=tid and k=tid+1024

    __shared__ float sh_mn[32];
    __shared__ float sh_mx[32];
    __shared__ float s_mn, s_mx;

    float vals[2];
    float lmn = 3.4e38f, lmx = -3.4e38f;

#pragma unroll
    for (int j = 0; j < 2; j++) {
        int k = tid + j * 1024;
        float s = 0.f;
#pragma unroll 8
        for (int c = 0; c < CHUNKS; c++) {
            s += g_partial[(size_t)(b * CHUNKS + c) * LL + k];
        }
        float v = s * (1.0f / (float)ROWS_PER_B);
        if (k == 0) v = 0.f;
        vals[j] = v;
        if (k != 0) {
            lmn = fminf(lmn, v);
            lmx = fmaxf(lmx, v);
        }
    }

    // block reduce min/max (1024 threads = 32 warps)
#pragma unroll
    for (int o = 16; o > 0; o >>= 1) {
        lmn = fminf(lmn, __shfl_down_sync(0xffffffffu, lmn, o));
        lmx = fmaxf(lmx, __shfl_down_sync(0xffffffffu, lmx, o));
    }
    if ((tid & 31) == 0) { sh_mn[tid >> 5] = lmn; sh_mx[tid >> 5] = lmx; }
    __syncthreads();
    if (tid < 32) {
        lmn = sh_mn[tid]; lmx = sh_mx[tid];
#pragma unroll
        for (int o = 16; o > 0; o >>= 1) {
            lmn = fminf(lmn, __shfl_down_sync(0xffffffffu, lmn, o));
            lmx = fmaxf(lmx, __shfl_down_sync(0xffffffffu, lmx, o));
        }
        if (tid == 0) { s_mn = lmn; s_mx = lmx; }
    }
    __syncthreads();

    float mn = s_mn, mx = s_mx;
#pragma unroll
    for (int j = 0; j < 2; j++) {
        int k = tid + j * 1024;
        float out = (k == 0) ? 1.0f : (vals[j] - mn) / mx;
        g_imp[b * LL + k] = out;
    }
}

// ---------------------------------------------------------------------------
// K4: LN1 row statistics (mean, rstd). One block (256 thr) per row.
// ---------------------------------------------------------------------------
__global__ void row_stats_kernel(const float* __restrict__ X) {
    int row = blockIdx.x;
    int tid = threadIdx.x;
    __shared__ float sh[8];
    __shared__ float s_bcast;

    float4 v = ((const float4*)(X + (size_t)row * DD))[tid];

    float s = v.x + v.y + v.z + v.w;
#pragma unroll
    for (int o = 16; o > 0; o >>= 1) s += __shfl_down_sync(0xffffffffu, s, o);
    if ((tid & 31) == 0) sh[tid >> 5] = s;
    __syncthreads();
    if (tid < 8) {
        s = sh[tid];
#pragma unroll
        for (int o = 4; o > 0; o >>= 1) s += __shfl_down_sync(0xffu, s, o);
        if (tid == 0) s_bcast = s;
    }
    __syncthreads();
    float m = s_bcast * (1.0f / (float)DD);

    float dx = v.x - m, dy = v.y - m, dz = v.z - m, dw = v.w - m;
    float sq = dx * dx + dy * dy + dz * dz + dw * dw;
#pragma unroll
    for (int o = 16; o > 0; o >>= 1) sq += __shfl_down_sync(0xffffffffu, sq, o);
    __syncthreads();
    if ((tid & 31) == 0) sh[tid >> 5] = sq;
    __syncthreads();
    if (tid < 8) {
        sq = sh[tid];
#pragma unroll
        for (int o = 4; o > 0; o >>= 1) sq += __shfl_down_sync(0xffu, sq, o);
        if (tid == 0) {
            float var = sq * (1.0f / (float)DD);
            g_mean[row] = m;
            g_rstd[row] = rsqrtf(var + 1e-5f);
        }
    }
}

// ---------------------------------------------------------------------------
// K5: fused LN1 + GEMM:  h1 = LN1(X) @ W1 + b1
// 128x128 block tile, BK=8, 256 threads, 8x8 per thread. LN applied on A load.
// DOUBLE-BUFFERED: prefetch tile k+1 into the idle SMEM buffer during compute
// on the active buffer; ONE __syncthreads per iteration.
// ---------------------------------------------------------------------------
__global__ void __launch_bounds__(256)
gemm_ln_kernel(const float* __restrict__ X, const float* __restrict__ W1,
               const float* __restrict__ g1, const float* __restrict__ b1ln,
               const float* __restrict__ bias1) {
    __shared__ float As[2][8][128];
    __shared__ float Bs[2][8][128];
    __shared__ float sg[DD];
    __shared__ float sbv[DD];

    int tid = threadIdx.x;
    int m0 = blockIdx.y * 128;
    int n0 = blockIdx.x * 128;

    for (int i = tid; i < DD; i += 256) { sg[i] = g1[i]; sbv[i] = b1ln[i]; }

    // A loader mapping: row = tid/2 (0..127), k-quad = (tid&1)*4
    int ar = tid >> 1;
    int ak = (tid & 1) * 4;
    float mrow = g_mean[m0 + ar];
    float rrow = g_rstd[m0 + ar];
    const float* Arow = X + (size_t)(m0 + ar) * DD;

    // B loader mapping: k = tid/32 (0..7), n-quad = (tid&31)*4
    int bk = tid >> 5;
    int bn = (tid & 31) * 4;
    const float* Bbase = W1 + (size_t)bk * DD + n0 + bn;

    int ty = tid >> 4;   // 0..15
    int tx = tid & 15;   // 0..15

    float acc[8][8];
#pragma unroll
    for (int i = 0; i < 8; i++)
#pragma unroll
        for (int j = 0; j < 8; j++) acc[i][j] = 0.f;

    __syncthreads();  // sg/sbv ready (also covers first-tile buffer below)

    // ---- prologue: load tile 0 into buffer 0 ----
    {
        float4 av = *(const float4*)(Arow + 0 + ak);
        As[0][ak + 0][ar] = (av.x - mrow) * rrow * sg[ak + 0] + sbv[ak + 0];
        As[0][ak + 1][ar] = (av.y - mrow) * rrow * sg[ak + 1] + sbv[ak + 1];
        As[0][ak + 2][ar] = (av.z - mrow) * rrow * sg[ak + 2] + sbv[ak + 2];
        As[0][ak + 3][ar] = (av.w - mrow) * rrow * sg[ak + 3] + sbv[ak + 3];
        float4 bv = *(const float4*)(Bbase);
        *(float4*)&Bs[0][bk][bn] = bv;
    }
    __syncthreads();

    int p = 0;
    for (int it = 0; it < DD / 8; it++) {
        // prefetch next tile into the idle buffer (no hazard: compute reads
        // buffer p, these stores write buffer 1-p; barrier at loop end)
        if (it < DD / 8 - 1) {
            int kt = (it + 1) * 8;
            float4 av = *(const float4*)(Arow + kt + ak);
            int q = p ^ 1;
            As[q][ak + 0][ar] = (av.x - mrow) * rrow * sg[kt + ak + 0] + sbv[kt + ak + 0];
            As[q][ak + 1][ar] = (av.y - mrow) * rrow * sg[kt + ak + 1] + sbv[kt + ak + 1];
            As[q][ak + 2][ar] = (av.z - mrow) * rrow * sg[kt + ak + 2] + sbv[kt + ak + 2];
            As[q][ak + 3][ar] = (av.w - mrow) * rrow * sg[kt + ak + 3] + sbv[kt + ak + 3];
            float4 bv = *(const float4*)(Bbase + (size_t)kt * DD);
            *(float4*)&Bs[q][bk][bn] = bv;
        }

#pragma unroll
        for (int k = 0; k < 8; k++) {
            float a[8], bfr[8];
            *(float4*)(a)       = *(float4*)&As[p][k][ty * 8];
            *(float4*)(a + 4)   = *(float4*)&As[p][k][ty * 8 + 4];
            *(float4*)(bfr)     = *(float4*)&Bs[p][k][tx * 8];
            *(float4*)(bfr + 4) = *(float4*)&Bs[p][k][tx * 8 + 4];
#pragma unroll
            for (int i = 0; i < 8; i++)
#pragma unroll
                for (int j = 0; j < 8; j++)
                    acc[i][j] += a[i] * bfr[j];
        }
        __syncthreads();
        p ^= 1;
    }

    // epilogue: + b1, store h1 (b1 is zeros in this problem but kept general)
    float bias[8];
#pragma unroll
    for (int j = 0; j < 8; j++) bias[j] = bias1[n0 + tx * 8 + j];

#pragma unroll
    for (int i = 0; i < 8; i++) {
        float* orow = g_h1 + (size_t)(m0 + ty * 8 + i) * DD + n0 + tx * 8;
        float4 lo, hi;
        lo.x = acc[i][0] + bias[0]; lo.y = acc[i][1] + bias[1];
        lo.z = acc[i][2] + bias[2]; lo.w = acc[i][3] + bias[3];
        hi.x = acc[i][4] + bias[4]; hi.y = acc[i][5] + bias[5];
        hi.z = acc[i][6] + bias[6]; hi.w = acc[i][7] + bias[7];
        *(float4*)(orow)     = lo;
        *(float4*)(orow + 4) = hi;
    }
}

// ---------------------------------------------------------------------------
// K6: per-row epilogue: LN2 -> GELU(exact) -> W2 dot -> +100 CLS bias ->
//     softmax -> final = (imp+learned)/2 -> straight-through mask.
//     Also writes attention_mask copy and tome ones. One block per row.
// ---------------------------------------------------------------------------
__global__ void epilogue_kernel(const float* __restrict__ attn,
                                const float* __restrict__ g2,
                                const float* __restrict__ b2ln,
                                const float* __restrict__ W2,
                                const float* __restrict__ b2,
                                float* __restrict__ out) {
    int row = blockIdx.x;    // b*LL + l
    int tid = threadIdx.x;   // 256
    __shared__ float sh[8];
    __shared__ float s_bcast;
    __shared__ float s_acc0, s_acc1;

    float4 v = ((const float4*)(g_h1 + (size_t)row * DD))[tid];

    // mean
    float s = v.x + v.y + v.z + v.w;
#pragma unroll
    for (int o = 16; o > 0; o >>= 1) s += __shfl_down_sync(0xffffffffu, s, o);
    if ((tid & 31) == 0) sh[tid >> 5] = s;
    __syncthreads();
    if (tid < 8) {
        s = sh[tid];
#pragma unroll
        for (int o = 4; o > 0; o >>= 1) s += __shfl_down_sync(0xffu, s, o);
        if (tid == 0) s_bcast = s;
    }
    __syncthreads();
    float m = s_bcast * (1.0f / (float)DD);

    // variance
    float dx[4];
    dx[0] = v.x - m; dx[1] = v.y - m; dx[2] = v.z - m; dx[3] = v.w - m;
    float sq = dx[0] * dx[0] + dx[1] * dx[1] + dx[2] * dx[2] + dx[3] * dx[3];
#pragma unroll
    for (int o = 16; o > 0; o >>= 1) sq += __shfl_down_sync(0xffffffffu, sq, o);
    __syncthreads();
    if ((tid & 31) == 0) sh[tid >> 5] = sq;
    __syncthreads();
    if (tid < 8) {
        sq = sh[tid];
#pragma unroll
        for (int o = 4; o > 0; o >>= 1) sq += __shfl_down_sync(0xffu, sq, o);
        if (tid == 0) s_bcast = sq;
    }
    __syncthreads();
    float rstd = rsqrtf(s_bcast * (1.0f / (float)DD) + 1e-5f);

    // GELU + dot with W2 columns
    float acc0 = 0.f, acc1 = 0.f;
#pragma unroll
    for (int j = 0; j < 4; j++) {
        int k = tid * 4 + j;
        float y = dx[j] * rstd * g2[k] + b2ln[k];
        float ge = 0.5f * y * (1.0f + erff(y * 0.70710678118654752f));
        acc0 += ge * W2[k * 2 + 0];
        acc1 += ge * W2[k * 2 + 1];
    }
#pragma unroll
    for (int o = 16; o > 0; o >>= 1) {
        acc0 += __shfl_down_sync(0xffffffffu, acc0, o);
        acc1 += __shfl_down_sync(0xffffffffu, acc1, o);
    }
    __syncthreads();
    if ((tid & 31) == 0) sh[tid >> 5] = acc0;
    __syncthreads();
    if (tid < 8) {
        acc0 = sh[tid];
#pragma unroll
        for (int o = 4; o > 0; o >>= 1) acc0 += __shfl_down_sync(0xffu, acc0, o);
        if (tid == 0) s_acc0 = acc0;
    }
    __syncthreads();
    if ((tid & 31) == 0) sh[tid >> 5] = acc1;
    __syncthreads();
    if (tid < 8) {
        acc1 = sh[tid];
#pragma unroll
        for (int o = 4; o > 0; o >>= 1) acc1 += __shfl_down_sync(0xffu, acc1, o);
        if (tid == 0) s_acc1 = acc1;
    }
    __syncthreads();

    if (tid == 0) {
        float l0 = s_acc0 + b2[0];
        float l1 = s_acc1 + b2[1];
        int l = row & (LL - 1);
        if (l == 0) l0 += 100.0f;   // CLS keep bias
        float mx = fmaxf(l0, l1);
        float e0 = __expf(l0 - mx);
        float e1 = __expf(l1 - mx);
        float learned = e0 / (e0 + e1);
        float fin = (g_imp[row] + learned) * 0.5f;
        float hard = (fin >= 0.5f) ? 1.0f : 0.0f;
        float maskv = (hard - fin) + fin;   // straight-through, faithful order

        out[OUT_MASK + row] = maskv;
        out[OUT_TOME + row] = 1.0f;
        out[OUT_ATTN + row] = attn[row];
    }
}

// ---------------------------------------------------------------------------
extern "C" void kernel_launch(void* const* d_in, const int* in_sizes, int n_in,
                              void* d_out, int out_size) {
    const float* hidden = (const float*)d_in[0];
    const float* attn   = (const float*)d_in[1];
    const float* scores = (const float*)d_in[2];
    // d_in[3] key_layer, d_in[4] tome_size: unused
    const float* ln1g = (const float*)d_in[5];
    const float* ln1b = (const float*)d_in[6];
    const float* W1   = (const float*)d_in[7];
    const float* b1   = (const float*)d_in[8];
    const float* ln2g = (const float*)d_in[9];
    const float* ln2b = (const float*)d_in[10];
    const float* W2   = (const float*)d_in[11];
    const float* b2   = (const float*)d_in[12];
    float* out = (float*)d_out;

    // 1. copy hidden_states -> out
    int n4 = (M_TOTAL * DD) / 4;
    copy_hidden_kernel<<<(n4 + 255) / 256, 256>>>(
        (const float4*)hidden, (float4*)(out + OUT_HID), n4);

    // 2. score reduction (partials)
    reduce_scores_kernel<<<dim3(2, CHUNKS, BB), 256>>>(scores);

    // 3. finalize importance
    finalize_imp_kernel<<<BB, 1024>>>();

    // 4. LN1 row stats
    row_stats_kernel<<<M_TOTAL, 256>>>(hidden);

    // 5. fused LN1 + GEMM (double-buffered)
    gemm_ln_kernel<<<dim3(DD / 128, M_TOTAL / 128), 256>>>(
        hidden, W1, ln1g, ln1b, b1);

    // 6. fused LN2/GELU/W2/softmax/mask epilogue (+ attn copy + tome ones)
    epilogue_kernel<<<M_TOTAL, 256>>>(attn, ln2g, ln2b, W2, b2, out);
}

// round 11
// speedup vs baseline: 1.2583x; 1.2583x over previous
#include <cuda_runtime.h>
#include <math.h>
#include <stdint.h>

// Problem constants
#define BB 4
#define HH 16
#define LL 2048
#define DD 1024
#define ROWS_PER_B (HH * LL)          // 32768 rows of length LL per batch
#define CHUNKS 128
#define ROWS_PER_CHUNK (ROWS_PER_B / CHUNKS)  // 256
#define M_TOTAL (BB * LL)             // 8192

// Output packing (flattened tuple)
#define OUT_HID   0
#define OUT_ATTN  (M_TOTAL * DD)            // 8388608
#define OUT_TOME  (OUT_ATTN + M_TOTAL)      // 8396800
#define OUT_MASK  (OUT_TOME + M_TOTAL)      // 8404992

// Fused-kernel role partition (gemm first: longest blocks start immediately)
#define GEMM_BLOCKS   512                    // 8 x 64 tile grid
#define REDUCE_BLOCKS 1024                   // 2 k-tiles x 128 chunks x 4 batch
#define COPY_BLOCKS   2048                   // 2M float4 / (256 thr * 4 each)
#define FUSED_BLOCKS  (GEMM_BLOCKS + REDUCE_BLOCKS + COPY_BLOCKS)

// Device scratch (static globals — no allocation allowed)
__device__ float g_partial[BB * CHUNKS * LL];   // 4 MB   score partial sums
__device__ float g_imp[BB * LL];                // 32 KB  normalized importance
__device__ float g_mean[M_TOTAL];               // LN1 row mean
__device__ float g_rstd[M_TOTAL];               // LN1 row rstd
__device__ float g_h1[(size_t)M_TOTAL * DD];    // 33.5 MB  GEMM output

// ---------------------------------------------------------------------------
// K4: LN1 row statistics (mean, rstd). One block (256 thr) per row.
// Must run BEFORE the fused kernel (gemm role consumes g_mean/g_rstd).
// ---------------------------------------------------------------------------
__global__ void row_stats_kernel(const float* __restrict__ X) {
    int row = blockIdx.x;
    int tid = threadIdx.x;
    __shared__ float sh[8];
    __shared__ float s_bcast;

    float4 v = ((const float4*)(X + (size_t)row * DD))[tid];

    float s = v.x + v.y + v.z + v.w;
#pragma unroll
    for (int o = 16; o > 0; o >>= 1) s += __shfl_down_sync(0xffffffffu, s, o);
    if ((tid & 31) == 0) sh[tid >> 5] = s;
    __syncthreads();
    if (tid < 8) {
        s = sh[tid];
#pragma unroll
        for (int o = 4; o > 0; o >>= 1) s += __shfl_down_sync(0xffu, s, o);
        if (tid == 0) s_bcast = s;
    }
    __syncthreads();
    float m = s_bcast * (1.0f / (float)DD);

    float dx = v.x - m, dy = v.y - m, dz = v.z - m, dw = v.w - m;
    float sq = dx * dx + dy * dy + dz * dz + dw * dw;
#pragma unroll
    for (int o = 16; o > 0; o >>= 1) sq += __shfl_down_sync(0xffffffffu, sq, o);
    __syncthreads();
    if ((tid & 31) == 0) sh[tid >> 5] = sq;
    __syncthreads();
    if (tid < 8) {
        sq = sh[tid];
#pragma unroll
        for (int o = 4; o > 0; o >>= 1) sq += __shfl_down_sync(0xffu, sq, o);
        if (tid == 0) {
            float var = sq * (1.0f / (float)DD);
            g_mean[row] = m;
            g_rstd[row] = rsqrtf(var + 1e-5f);
        }
    }
}

// ---------------------------------------------------------------------------
// FUSED heterogeneous kernel: three independent roles selected by blockIdx.x.
//  [0, 512)            GEMM:  h1 = LN1(X) @ W1 + b1   (FMA-bound)
//  [512, 1536)         score partial reduction        (DRAM-bound)
//  [1536, 3584)        hidden_states copy to out      (DRAM-bound)
// The CTA scheduler interleaves roles across SM slots, overlapping the
// DRAM-bound work (~1.16 GB) with the FMA-bound GEMM.
// ---------------------------------------------------------------------------
__global__ void __launch_bounds__(256)
fused_main_kernel(const float* __restrict__ X, const float* __restrict__ W1,
                  const float* __restrict__ g1, const float* __restrict__ b1ln,
                  const float* __restrict__ bias1,
                  const float* __restrict__ scores,
                  float* __restrict__ out_hid) {
    int bid = blockIdx.x;
    int tid = threadIdx.x;

    if (bid < GEMM_BLOCKS) {
        // ================= GEMM role (double-buffered SGEMM) =================
        __shared__ float As[2][8][128];
        __shared__ float Bs[2][8][128];
        __shared__ float sg[DD];
        __shared__ float sbv[DD];

        int m0 = (bid >> 3) * 128;      // 64 tiles along M
        int n0 = (bid & 7) * 128;       // 8 tiles along N

        for (int i = tid; i < DD; i += 256) { sg[i] = g1[i]; sbv[i] = b1ln[i]; }

        int ar = tid >> 1;
        int ak = (tid & 1) * 4;
        float mrow = g_mean[m0 + ar];
        float rrow = g_rstd[m0 + ar];
        const float* Arow = X + (size_t)(m0 + ar) * DD;

        int bk = tid >> 5;
        int bn = (tid & 31) * 4;
        const float* Bbase = W1 + (size_t)bk * DD + n0 + bn;

        int ty = tid >> 4;
        int tx = tid & 15;

        float acc[8][8];
#pragma unroll
        for (int i = 0; i < 8; i++)
#pragma unroll
            for (int j = 0; j < 8; j++) acc[i][j] = 0.f;

        __syncthreads();  // sg/sbv ready

        // prologue: tile 0 -> buffer 0
        {
            float4 av = *(const float4*)(Arow + ak);
            As[0][ak + 0][ar] = (av.x - mrow) * rrow * sg[ak + 0] + sbv[ak + 0];
            As[0][ak + 1][ar] = (av.y - mrow) * rrow * sg[ak + 1] + sbv[ak + 1];
            As[0][ak + 2][ar] = (av.z - mrow) * rrow * sg[ak + 2] + sbv[ak + 2];
            As[0][ak + 3][ar] = (av.w - mrow) * rrow * sg[ak + 3] + sbv[ak + 3];
            float4 bv = *(const float4*)(Bbase);
            *(float4*)&Bs[0][bk][bn] = bv;
        }
        __syncthreads();

        int p = 0;
        for (int it = 0; it < DD / 8; it++) {
            if (it < DD / 8 - 1) {
                int kt = (it + 1) * 8;
                float4 av = *(const float4*)(Arow + kt + ak);
                int q = p ^ 1;
                As[q][ak + 0][ar] = (av.x - mrow) * rrow * sg[kt + ak + 0] + sbv[kt + ak + 0];
                As[q][ak + 1][ar] = (av.y - mrow) * rrow * sg[kt + ak + 1] + sbv[kt + ak + 1];
                As[q][ak + 2][ar] = (av.z - mrow) * rrow * sg[kt + ak + 2] + sbv[kt + ak + 2];
                As[q][ak + 3][ar] = (av.w - mrow) * rrow * sg[kt + ak + 3] + sbv[kt + ak + 3];
                float4 bv = *(const float4*)(Bbase + (size_t)kt * DD);
                *(float4*)&Bs[q][bk][bn] = bv;
            }

#pragma unroll
            for (int k = 0; k < 8; k++) {
                float a[8], bfr[8];
                *(float4*)(a)       = *(float4*)&As[p][k][ty * 8];
                *(float4*)(a + 4)   = *(float4*)&As[p][k][ty * 8 + 4];
                *(float4*)(bfr)     = *(float4*)&Bs[p][k][tx * 8];
                *(float4*)(bfr + 4) = *(float4*)&Bs[p][k][tx * 8 + 4];
#pragma unroll
                for (int i = 0; i < 8; i++)
#pragma unroll
                    for (int j = 0; j < 8; j++)
                        acc[i][j] += a[i] * bfr[j];
            }
            __syncthreads();
            p ^= 1;
        }

        float bias[8];
#pragma unroll
        for (int j = 0; j < 8; j++) bias[j] = bias1[n0 + tx * 8 + j];

#pragma unroll
        for (int i = 0; i < 8; i++) {
            float* orow = g_h1 + (size_t)(m0 + ty * 8 + i) * DD + n0 + tx * 8;
            float4 lo, hi;
            lo.x = acc[i][0] + bias[0]; lo.y = acc[i][1] + bias[1];
            lo.z = acc[i][2] + bias[2]; lo.w = acc[i][3] + bias[3];
            hi.x = acc[i][4] + bias[4]; hi.y = acc[i][5] + bias[5];
            hi.z = acc[i][6] + bias[6]; hi.w = acc[i][7] + bias[7];
            *(float4*)(orow)     = lo;
            *(float4*)(orow + 4) = hi;
        }
    } else if (bid < GEMM_BLOCKS + REDUCE_BLOCKS) {
        // ================= score-reduction role =================
        int id = bid - GEMM_BLOCKS;         // 0..1023
        int kx = id & 1;                    // k-tile of 1024
        int chunk = (id >> 1) & 127;        // row chunk
        int b = id >> 8;                    // batch

        int k = kx * 1024 + tid * 4;
        const float* base = scores +
            ((size_t)(b * ROWS_PER_B + chunk * ROWS_PER_CHUNK)) * LL + k;

        float ax = 0.f, ay = 0.f, az = 0.f, aw = 0.f;
#pragma unroll 8
        for (int r = 0; r < ROWS_PER_CHUNK; r++) {
            float4 v = *(const float4*)(base + (size_t)r * LL);
            ax += v.x; ay += v.y; az += v.z; aw += v.w;
        }
        float4 o; o.x = ax; o.y = ay; o.z = az; o.w = aw;
        *(float4*)&g_partial[(size_t)(b * CHUNKS + chunk) * LL + k] = o;
    } else {
        // ================= hidden-states copy role =================
        int id = bid - GEMM_BLOCKS - REDUCE_BLOCKS;   // 0..2047
        const float4* src = (const float4*)X;
        float4* dst = (float4*)out_hid;
        int base = id * 1024 + tid;                   // 1024 float4 per block
#pragma unroll
        for (int j = 0; j < 4; j++) {
            int i = base + j * 256;
            dst[i] = src[i];
        }
    }
}

// ---------------------------------------------------------------------------
// K3: finalize importance (combine partials, min/max normalize).
// One block (1024 thr) per batch.
// ---------------------------------------------------------------------------
__global__ void finalize_imp_kernel() {
    int b = blockIdx.x;
    int tid = threadIdx.x;

    __shared__ float sh_mn[32];
    __shared__ float sh_mx[32];
    __shared__ float s_mn, s_mx;

    float vals[2];
    float lmn = 3.4e38f, lmx = -3.4e38f;

#pragma unroll
    for (int j = 0; j < 2; j++) {
        int k = tid + j * 1024;
        float s = 0.f;
#pragma unroll 8
        for (int c = 0; c < CHUNKS; c++) {
            s += g_partial[(size_t)(b * CHUNKS + c) * LL + k];
        }
        float v = s * (1.0f / (float)ROWS_PER_B);
        if (k == 0) v = 0.f;
        vals[j] = v;
        if (k != 0) {
            lmn = fminf(lmn, v);
            lmx = fmaxf(lmx, v);
        }
    }

#pragma unroll
    for (int o = 16; o > 0; o >>= 1) {
        lmn = fminf(lmn, __shfl_down_sync(0xffffffffu, lmn, o));
        lmx = fmaxf(lmx, __shfl_down_sync(0xffffffffu, lmx, o));
    }
    if ((tid & 31) == 0) { sh_mn[tid >> 5] = lmn; sh_mx[tid >> 5] = lmx; }
    __syncthreads();
    if (tid < 32) {
        lmn = sh_mn[tid]; lmx = sh_mx[tid];
#pragma unroll
        for (int o = 16; o > 0; o >>= 1) {
            lmn = fminf(lmn, __shfl_down_sync(0xffffffffu, lmn, o));
            lmx = fmaxf(lmx, __shfl_down_sync(0xffffffffu, lmx, o));
        }
        if (tid == 0) { s_mn = lmn; s_mx = lmx; }
    }
    __syncthreads();

    float mn = s_mn, mx = s_mx;
#pragma unroll
    for (int j = 0; j < 2; j++) {
        int k = tid + j * 1024;
        float out = (k == 0) ? 1.0f : (vals[j] - mn) / mx;
        g_imp[b * LL + k] = out;
    }
}

// ---------------------------------------------------------------------------
// K6: per-row epilogue: LN2 -> GELU(exact) -> W2 dot -> +100 CLS bias ->
//     softmax -> final = (imp+learned)/2 -> straight-through mask.
//     Also writes attention_mask copy and tome ones. One block per row.
// ---------------------------------------------------------------------------
__global__ void epilogue_kernel(const float* __restrict__ attn,
                                const float* __restrict__ g2,
                                const float* __restrict__ b2ln,
                                const float* __restrict__ W2,
                                const float* __restrict__ b2,
                                float* __restrict__ out) {
    int row = blockIdx.x;
    int tid = threadIdx.x;
    __shared__ float sh[8];
    __shared__ float s_bcast;
    __shared__ float s_acc0, s_acc1;

    float4 v = ((const float4*)(g_h1 + (size_t)row * DD))[tid];

    float s = v.x + v.y + v.z + v.w;
#pragma unroll
    for (int o = 16; o > 0; o >>= 1) s += __shfl_down_sync(0xffffffffu, s, o);
    if ((tid & 31) == 0) sh[tid >> 5] = s;
    __syncthreads();
    if (tid < 8) {
        s = sh[tid];
#pragma unroll
        for (int o = 4; o > 0; o >>= 1) s += __shfl_down_sync(0xffu, s, o);
        if (tid == 0) s_bcast = s;
    }
    __syncthreads();
    float m = s_bcast * (1.0f / (float)DD);

    float dx[4];
    dx[0] = v.x - m; dx[1] = v.y - m; dx[2] = v.z - m; dx[3] = v.w - m;
    float sq = dx[0] * dx[0] + dx[1] * dx[1] + dx[2] * dx[2] + dx[3] * dx[3];
#pragma unroll
    for (int o = 16; o > 0; o >>= 1) sq += __shfl_down_sync(0xffffffffu, sq, o);
    __syncthreads();
    if ((tid & 31) == 0) sh[tid >> 5] = sq;
    __syncthreads();
    if (tid < 8) {
        sq = sh[tid];
#pragma unroll
        for (int o = 4; o > 0; o >>= 1) sq += __shfl_down_sync(0xffu, sq, o);
        if (tid == 0) s_bcast = sq;
    }
    __syncthreads();
    float rstd = rsqrtf(s_bcast * (1.0f / (float)DD) + 1e-5f);

    float acc0 = 0.f, acc1 = 0.f;
#pragma unroll
    for (int j = 0; j < 4; j++) {
        int k = tid * 4 + j;
        float y = dx[j] * rstd * g2[k] + b2ln[k];
        float ge = 0.5f * y * (1.0f + erff(y * 0.70710678118654752f));
        acc0 += ge * W2[k * 2 + 0];
        acc1 += ge * W2[k * 2 + 1];
    }
#pragma unroll
    for (int o = 16; o > 0; o >>= 1) {
        acc0 += __shfl_down_sync(0xffffffffu, acc0, o);
        acc1 += __shfl_down_sync(0xffffffffu, acc1, o);
    }
    __syncthreads();
    if ((tid & 31) == 0) sh[tid >> 5] = acc0;
    __syncthreads();
    if (tid < 8) {
        acc0 = sh[tid];
#pragma unroll
        for (int o = 4; o > 0; o >>= 1) acc0 += __shfl_down_sync(0xffu, acc0, o);
        if (tid == 0) s_acc0 = acc0;
    }
    __syncthreads();
    if ((tid & 31) == 0) sh[tid >> 5] = acc1;
    __syncthreads();
    if (tid < 8) {
        acc1 = sh[tid];
#pragma unroll
        for (int o = 4; o > 0; o >>= 1) acc1 += __shfl_down_sync(0xffu, acc1, o);
        if (tid == 0) s_acc1 = acc1;
    }
    __syncthreads();

    if (tid == 0) {
        float l0 = s_acc0 + b2[0];
        float l1 = s_acc1 + b2[1];
        int l = row & (LL - 1);
        if (l == 0) l0 += 100.0f;   // CLS keep bias
        float mx = fmaxf(l0, l1);
        float e0 = __expf(l0 - mx);
        float e1 = __expf(l1 - mx);
        float learned = e0 / (e0 + e1);
        float fin = (g_imp[row] + learned) * 0.5f;
        float hard = (fin >= 0.5f) ? 1.0f : 0.0f;
        float maskv = (hard - fin) + fin;   // straight-through, faithful order

        out[OUT_MASK + row] = maskv;
        out[OUT_TOME + row] = 1.0f;
        out[OUT_ATTN + row] = attn[row];
    }
}

// ---------------------------------------------------------------------------
extern "C" void kernel_launch(void* const* d_in, const int* in_sizes, int n_in,
                              void* d_out, int out_size) {
    const float* hidden = (const float*)d_in[0];
    const float* attn   = (const float*)d_in[1];
    const float* scores = (const float*)d_in[2];
    // d_in[3] key_layer, d_in[4] tome_size: unused
    const float* ln1g = (const float*)d_in[5];
    const float* ln1b = (const float*)d_in[6];
    const float* W1   = (const float*)d_in[7];
    const float* b1   = (const float*)d_in[8];
    const float* ln2g = (const float*)d_in[9];
    const float* ln2b = (const float*)d_in[10];
    const float* W2   = (const float*)d_in[11];
    const float* b2   = (const float*)d_in[12];
    float* out = (float*)d_out;

    // 1. LN1 row stats (prerequisite of the fused GEMM role)
    row_stats_kernel<<<M_TOTAL, 256>>>(hidden);

    // 2. fused heterogeneous kernel: GEMM + score reduction + hidden copy
    fused_main_kernel<<<FUSED_BLOCKS, 256>>>(
        hidden, W1, ln1g, ln1b, b1, scores, out + OUT_HID);

    // 3. finalize importance (needs reduce partials)
    finalize_imp_kernel<<<BB, 1024>>>();

    // 4. fused LN2/GELU/W2/softmax/mask epilogue (+ attn copy + tome ones)
    epilogue_kernel<<<M_TOTAL, 256>>>(attn, ln2g, ln2b, W2, b2, out);
}